// round 2
// baseline (speedup 1.0000x reference)
#include <cuda_runtime.h>
#include <cuda_bf16.h>

// HMM forward, scaled probability domain, fully warp-autonomous persistent kernel.
//
//   w_t[j] = (sum_i w_{t-1}[i] * exp(trans[i,j])) * inv_norm * exp(emit[j,obs[t]])
//   out    = log(sum_j w_final[j]) + sum log(norm)
//
// Synchronization: NO barriers, NO counters. w values are strictly positive;
// each stored word carries the step phase in its SIGN BIT (buffer = t&1,
// sign = (t>>1)&1). Polling the data is the synchronization: a reader accepts
// a word only when its sign matches the expected phase. Buffer reuse at
// distance 4 (same buffer+sign) is impossible to race: the writer of step t+4
// data-depends on step t+3 values, which depend on t+2, t+1, and finally on
// the reader's OWN t+1 chunk, which it writes only after finishing reading
// step t. Each word is a single 32-bit atomic unit (flag == payload).
//
// Each warp owns 4 output columns; its exp(trans) slice (4 x 1024) lives in
// REGISTERS (128/lane), and the full w vector lives in registers (32/lane).
// Zero shared memory, zero __syncthreads in the 8191-step loop.

#define S     1024
#define NOBS  4096
#define TT    8192
#define NCTA  64
#define NTHR  128            // 4 warps per CTA; 256 warps total = S/4 columns

__device__ __align__(16) float        g_emitT[TT * S];  // exp(emit[j, obs[t]]), [t][j]
__device__ __align__(16) unsigned int g_w[2][S];        // sign-tagged positive floats

__device__ __forceinline__ uint4 ld_vol_v4(const unsigned int* p) {
    uint4 v;
    asm volatile("ld.volatile.global.v4.u32 {%0,%1,%2,%3}, [%4];"
                 : "=r"(v.x), "=r"(v.y), "=r"(v.z), "=r"(v.w) : "l"(p) : "memory");
    return v;
}
__device__ __forceinline__ void st_rel_u32(unsigned int* p, unsigned int v) {
    asm volatile("st.relaxed.gpu.global.u32 [%0], %1;" :: "l"(p), "r"(v) : "memory");
}

// Prologue: gather exp(emit) per timestep; write w0 into buffer 0, phase sign 0.
__global__ void hmm_init_kernel(const int* __restrict__ obs,
                                const float* __restrict__ start,
                                const float* __restrict__ emit) {
    long idx = (long)blockIdx.x * blockDim.x + threadIdx.x;
    if (idx >= (long)TT * S) return;
    int t = (int)(idx >> 10);
    int j = (int)(idx & (S - 1));
    float e = expf(emit[(long)j * NOBS + obs[t]]);
    g_emitT[idx] = e;
    if (t == 0) {
        float v = fmaxf(expf(start[j]) * e, 1e-33f);     // strictly positive
        g_w[0][j] = __float_as_uint(v);                  // sign 0 == phase of t=0
    }
}

__global__ void __launch_bounds__(NTHR, 1)
hmm_main_kernel(const float* __restrict__ trans, float* __restrict__ out) {
    const int lane = threadIdx.x & 31;
    const int wid  = threadIdx.x >> 5;
    const int gw   = blockIdx.x * (NTHR / 32) + wid;     // global warp id, 0..255
    const int c0   = gw << 2;                            // base output column
    const int mycol = c0 + lane;                         // valid when lane < 4

    // ---- Load this warp's exp(trans) slice into registers ----
    // P[c][r*4+u] pairs with w index i = 128*r + 4*lane + u.
    float P[4][32];
    #pragma unroll
    for (int c = 0; c < 4; ++c) {
        #pragma unroll
        for (int r = 0; r < 8; ++r) {
            #pragma unroll
            for (int u = 0; u < 4; ++u) {
                int i = (r << 7) + (lane << 2) + u;
                P[c][(r << 2) + u] = expf(__ldg(&trans[(long)i * S + c0 + c]));
            }
        }
    }

    float e_c = 0.0f;
    if (lane < 4) e_c = __ldg(&g_emitT[1 * S + mycol]);  // emission for t=1

    float logscale = 0.0f;
    float w[32];

    for (int t = 1; t < TT; ++t) {
        const unsigned esbit = (((unsigned)(t - 1) >> 1) & 1u) << 31;  // expected sign
        const unsigned int* rbuf = g_w[(t - 1) & 1] + (lane << 2);

        // ---- Poll: data IS the sync. Re-load only pending 16B granules. ----
        bool done[8];
        #pragma unroll
        for (int r = 0; r < 8; ++r) done[r] = false;
        for (;;) {
            bool all = true;
            #pragma unroll
            for (int r = 0; r < 8; ++r) {
                if (!done[r]) {
                    uint4 v = ld_vol_v4(rbuf + (r << 7));
                    unsigned bad = ((v.x ^ esbit) | (v.y ^ esbit) |
                                    (v.z ^ esbit) | (v.w ^ esbit)) & 0x80000000u;
                    if (!bad) {
                        w[(r << 2) + 0] = __uint_as_float(v.x & 0x7fffffffu);
                        w[(r << 2) + 1] = __uint_as_float(v.y & 0x7fffffffu);
                        w[(r << 2) + 2] = __uint_as_float(v.z & 0x7fffffffu);
                        w[(r << 2) + 3] = __uint_as_float(v.w & 0x7fffffffu);
                        done[r] = true;
                    } else {
                        all = false;
                    }
                }
            }
            if (all) break;
        }

        // Prefetch next step's emission while compute runs.
        float e_n = 0.0f;
        if (lane < 4) {
            int tn = (t + 1 < TT) ? t + 1 : TT - 1;
            e_n = __ldg(&g_emitT[tn * S + mycol]);
        }

        // ---- Periodic rescale: every warp holds the FULL w vector. ----
        float inv = 1.0f;
        if (((t - 1) & 7) == 0) {
            float m = w[0];
            #pragma unroll
            for (int k = 1; k < 32; ++k) m = fmaxf(m, w[k]);
            #pragma unroll
            for (int off = 16; off; off >>= 1)
                m = fmaxf(m, __shfl_xor_sync(0xffffffffu, m, off));
            inv = 1.0f / m;
            logscale += logf(m);
        }

        // ---- GEMV: 128 FFMA, 8 independent accumulator chains. ----
        float a0a = 0.f, a0b = 0.f, a1a = 0.f, a1b = 0.f;
        float a2a = 0.f, a2b = 0.f, a3a = 0.f, a3b = 0.f;
        #pragma unroll
        for (int k = 0; k < 32; k += 2) {
            float w0 = w[k], w1 = w[k + 1];
            a0a += w0 * P[0][k]; a0b += w1 * P[0][k + 1];
            a1a += w0 * P[1][k]; a1b += w1 * P[1][k + 1];
            a2a += w0 * P[2][k]; a2b += w1 * P[2][k + 1];
            a3a += w0 * P[3][k]; a3b += w1 * P[3][k + 1];
        }
        float a0 = a0a + a0b, a1 = a1a + a1b, a2 = a2a + a2b, a3 = a3a + a3b;

        #pragma unroll
        for (int off = 16; off; off >>= 1) {
            a0 += __shfl_xor_sync(0xffffffffu, a0, off);
            a1 += __shfl_xor_sync(0xffffffffu, a1, off);
            a2 += __shfl_xor_sync(0xffffffffu, a2, off);
            a3 += __shfl_xor_sync(0xffffffffu, a3, off);
        }

        if (lane < 4) {
            float av = (lane == 0) ? a0 : (lane == 1) ? a1 : (lane == 2) ? a2 : a3;
            float outv = fmaxf(av * inv * e_c, 1e-33f);   // keep strictly positive
            unsigned tag = (((unsigned)t >> 1) & 1u) << 31;
            st_rel_u32(&g_w[t & 1][mycol], __float_as_uint(outv) | tag);
        }
        e_c = e_n;
    }

    // ---- Epilogue: block 0 / warp 0 polls the final vector and reduces. ----
    if (blockIdx.x == 0 && wid == 0) {
        const unsigned esbit = (((unsigned)(TT - 1) >> 1) & 1u) << 31;
        const unsigned int* rbuf = g_w[(TT - 1) & 1] + (lane << 2);
        bool done[8];
        #pragma unroll
        for (int r = 0; r < 8; ++r) done[r] = false;
        for (;;) {
            bool all = true;
            #pragma unroll
            for (int r = 0; r < 8; ++r) {
                if (!done[r]) {
                    uint4 v = ld_vol_v4(rbuf + (r << 7));
                    unsigned bad = ((v.x ^ esbit) | (v.y ^ esbit) |
                                    (v.z ^ esbit) | (v.w ^ esbit)) & 0x80000000u;
                    if (!bad) {
                        w[(r << 2) + 0] = __uint_as_float(v.x & 0x7fffffffu);
                        w[(r << 2) + 1] = __uint_as_float(v.y & 0x7fffffffu);
                        w[(r << 2) + 2] = __uint_as_float(v.z & 0x7fffffffu);
                        w[(r << 2) + 3] = __uint_as_float(v.w & 0x7fffffffu);
                        done[r] = true;
                    } else {
                        all = false;
                    }
                }
            }
            if (all) break;
        }
        float s = 0.0f;
        #pragma unroll
        for (int k = 0; k < 32; ++k) s += w[k];
        #pragma unroll
        for (int off = 16; off; off >>= 1)
            s += __shfl_xor_sync(0xffffffffu, s, off);
        if (lane == 0) out[0] = logf(s) + logscale;
    }
}

extern "C" void kernel_launch(void* const* d_in, const int* in_sizes, int n_in,
                              void* d_out, int out_size) {
    const int*   obs   = (const int*)d_in[0];
    const float* start = (const float*)d_in[1];
    const float* trans = (const float*)d_in[2];
    const float* emit  = (const float*)d_in[3];
    float*       out   = (float*)d_out;

    (void)in_sizes; (void)n_in; (void)out_size;

    const int init_blocks = (TT * S + 255) / 256;
    hmm_init_kernel<<<init_blocks, 256>>>(obs, start, emit);
    hmm_main_kernel<<<NCTA, NTHR>>>(trans, out);
}